// round 1
// baseline (speedup 1.0000x reference)
#include <cuda_runtime.h>
#include <cuda_bf16.h>
#include <stdint.h>

#ifndef CLAMP_VAL
#define CLAMP_VAL 10000.0f
#endif

__device__ __forceinline__ float clampv(float v) {
    return fminf(fmaxf(v, -CLAMP_VAL), CLAMP_VAL);
}

// out flat index o -> row = o / out_w, col = o % out_w.
// For col < out_w-1: out = x[row*in_w + col]  (note x index = o + row when in_w = out_w+1)
// For col == out_w-1: out = mean(x[row*in_w + col .. row*in_w + in_w-1])
__global__ void __launch_bounds__(256)
binagg_copy_kernel(const float* __restrict__ x, float* __restrict__ out,
                   int in_w, int out_w, unsigned int n_vec)
{
    unsigned int v = blockIdx.x * blockDim.x + threadIdx.x;
    if (v >= n_vec) return;

    unsigned int o = v * 4u;                 // flat output index of first lane
    unsigned int row = o / (unsigned int)out_w;      // magic-multiply division
    unsigned int col = o - row * (unsigned int)out_w;

    if (col + 4u <= (unsigned int)(out_w - 1)) {
        // Fast path: 4 plain copies from the same input row.
        const float* src = x + (size_t)row * (size_t)in_w + col;
        float4 r;
        r.x = clampv(__ldg(src + 0));
        r.y = clampv(__ldg(src + 1));
        r.z = clampv(__ldg(src + 2));
        r.w = clampv(__ldg(src + 3));
        *reinterpret_cast<float4*>(out + o) = r;
    } else {
        // Boundary path: per-element, handles the averaged last node and row crossing.
        float inv_cnt = 1.0f / (float)(in_w - out_w + 1);
        #pragma unroll
        for (int j = 0; j < 4; ++j) {
            unsigned int oo = o + (unsigned int)j;
            unsigned int r  = oo / (unsigned int)out_w;
            unsigned int c  = oo - r * (unsigned int)out_w;
            const float* xr = x + (size_t)r * (size_t)in_w;
            float val;
            if (c < (unsigned int)(out_w - 1)) {
                val = __ldg(xr + c);
            } else {
                float s = 0.0f;
                for (int k = out_w - 1; k < in_w; ++k) s += __ldg(xr + k);
                val = s * inv_cnt;
            }
            out[oo] = clampv(val);
        }
    }
}

extern "C" void kernel_launch(void* const* d_in, const int* in_sizes, int n_in,
                              void* d_out, int out_size)
{
    const float* x = (const float*)d_in[0];
    float* out = (float*)d_out;

    // Known problem shape: batch=4096, in_width=8192. Derive defensively.
    const int in_w = 8192;
    int batch = in_sizes[0] / in_w;
    if (batch <= 0) batch = 1;
    int out_w = out_size / batch;

    unsigned int total = (unsigned int)out_size;          // 33,550,336 < 2^31
    unsigned int n_vec = (total + 3u) / 4u;               // exactly divisible here

    const int threads = 256;
    unsigned int blocks = (n_vec + threads - 1) / threads;
    binagg_copy_kernel<<<blocks, threads>>>(x, out, in_w, out_w, n_vec);
}

// round 2
// speedup vs baseline: 1.0882x; 1.0882x over previous
#include <cuda_runtime.h>
#include <cuda_bf16.h>
#include <stdint.h>

#ifndef CLAMP_VAL
#define CLAMP_VAL 10000.0f
#endif

__device__ __forceinline__ float clampv(float v) {
    return fminf(fmaxf(v, -CLAMP_VAL), CLAMP_VAL);
}

// ---------------------------------------------------------------------------
// Fast path kernel for the known shape: in_w = 8192 (power-of-2 vectors/row),
// out_w = in_w - 1. Index by INPUT float4 vectors: row = v>>11, colvec = v&2047.
// One aligned LDG.128 per vector, 4 coalesced scalar stores (3 + avg on the
// row-final vector). VPT vectors per thread, loads front-batched for MLP.
// ---------------------------------------------------------------------------
constexpr int VPT = 4;          // float4 vectors per thread
constexpr int TPB = 256;        // threads per block
constexpr unsigned VEC_PER_ROW_LOG2 = 11;      // 8192/4 = 2048 = 1<<11
constexpr unsigned VEC_PER_ROW_MASK = 2047u;

__global__ void __launch_bounds__(TPB)
binagg_fast_kernel(const float4* __restrict__ x, float* __restrict__ out,
                   unsigned n_vec, unsigned out_w)
{
    unsigned base = blockIdx.x * (TPB * VPT) + threadIdx.x;

    float4 r[VPT];
    unsigned v[VPT];
    #pragma unroll
    for (int i = 0; i < VPT; ++i) {
        v[i] = base + i * TPB;
        if (v[i] < n_vec) r[i] = __ldcs(&x[v[i]]);
    }

    #pragma unroll
    for (int i = 0; i < VPT; ++i) {
        if (v[i] >= n_vec) continue;
        unsigned row = v[i] >> VEC_PER_ROW_LOG2;
        unsigned cv  = v[i] & VEC_PER_ROW_MASK;
        float* o = out + (size_t)row * (size_t)out_w + (cv << 2);
        if (cv != VEC_PER_ROW_MASK) {
            __stcs(o + 0, clampv(r[i].x));
            __stcs(o + 1, clampv(r[i].y));
            __stcs(o + 2, clampv(r[i].z));
            __stcs(o + 3, clampv(r[i].w));
        } else {
            // input cols 8188..8191 -> out 8188, 8189, and 8190 = mean(z, w)
            __stcs(o + 0, clampv(r[i].x));
            __stcs(o + 1, clampv(r[i].y));
            __stcs(o + 2, clampv((r[i].z + r[i].w) * 0.5f));
        }
    }
}

// ---------------------------------------------------------------------------
// Generic fallback (any in_w/out_w): flat output indexing, scalar.
// ---------------------------------------------------------------------------
__global__ void __launch_bounds__(256)
binagg_generic_kernel(const float* __restrict__ x, float* __restrict__ out,
                      int in_w, int out_w, unsigned total)
{
    unsigned oo = blockIdx.x * blockDim.x + threadIdx.x;
    if (oo >= total) return;
    unsigned r = oo / (unsigned)out_w;
    unsigned c = oo - r * (unsigned)out_w;
    const float* xr = x + (size_t)r * (size_t)in_w;
    float val;
    if (c < (unsigned)(out_w - 1)) {
        val = __ldg(xr + c);
    } else {
        float s = 0.0f;
        for (int k = out_w - 1; k < in_w; ++k) s += __ldg(xr + k);
        val = s / (float)(in_w - out_w + 1);
    }
    out[oo] = clampv(val);
}

extern "C" void kernel_launch(void* const* d_in, const int* in_sizes, int n_in,
                              void* d_out, int out_size)
{
    const float* x = (const float*)d_in[0];
    float* out = (float*)d_out;

    const int in_w = 8192;
    int batch = in_sizes[0] / in_w;
    int out_w = (batch > 0) ? out_size / batch : 0;

    bool fast = (batch > 0) &&
                (batch * in_w == in_sizes[0]) &&
                (out_w == in_w - 1) &&
                ((size_t)batch * (size_t)out_w == (size_t)out_size);

    if (fast) {
        unsigned n_vec = (unsigned)((size_t)batch * (in_w / 4));   // 8,388,608
        unsigned vec_per_block = TPB * VPT;                        // 1024
        unsigned blocks = (n_vec + vec_per_block - 1) / vec_per_block;
        binagg_fast_kernel<<<blocks, TPB>>>(
            (const float4*)x, out, n_vec, (unsigned)out_w);
    } else {
        // Generic fallback: recover in_w/out_w as best we can.
        int iw = in_sizes[0];
        int ow = out_size;
        int b = 1;
        // try to infer batch by gcd-ish heuristic: assume square-ish batch rows
        for (int cand = 8192; cand >= 1; cand >>= 1) {
            if (in_sizes[0] % cand == 0) {
                int bb = in_sizes[0] / cand;
                if (bb > 0 && out_size % bb == 0) { b = bb; iw = cand; ow = out_size / bb; break; }
            }
        }
        unsigned total = (unsigned)out_size;
        unsigned blocks = (total + 255) / 256;
        binagg_generic_kernel<<<blocks, 256>>>(x, out, iw, ow, total);
    }
}